// round 8
// baseline (speedup 1.0000x reference)
#include <cuda_runtime.h>
#include <cuda_fp16.h>
#include <cstdint>

#define Hd 1024
#define Fd 2048
#define Td 8192

// ---------------- scratch (__device__ globals; no allocs allowed) -------------
__device__ __align__(16) float g_wts[Td * 4];    // w0, w1, w2, w1+w2
__device__ __align__(16) float g_cvec[2][Fd];    // b_d @ ad_w1 + ad_b1
__device__ __align__(16) __half g_xh[(size_t)Td * Hd];   // norm(x) fp16
__device__ __align__(16) __half g_Bb[(size_t)Fd * Hd];   // (W1*s_book)^T fp16
__device__ __align__(16) __half g_Bi[(size_t)Fd * Hd];   // (W1*s_iwslt)^T fp16
__device__ __align__(16) __half g_W2[(size_t)Hd * Fd];   // W2^T fp16
__device__ __align__(16) __half g_g[(size_t)Td * Fd];    // combined activation fp16

// ---------------- PTX helpers -------------------------------------------------
__device__ __forceinline__ uint32_t smem_u32(const void* p) {
    uint32_t a;
    asm("{ .reg .u64 t; cvta.to.shared.u64 t, %1; cvt.u32.u64 %0, t; }"
        : "=r"(a) : "l"(p));
    return a;
}
#define CP16(dst, src) \
    asm volatile("cp.async.cg.shared.global [%0], [%1], 16;" \
                 :: "r"(dst), "l"(__cvta_generic_to_global(src)))
#define CP_COMMIT() asm volatile("cp.async.commit_group;" ::: "memory")
#define CP_WAITG(n) asm volatile("cp.async.wait_group %0;" :: "n"(n) : "memory")
#define LDSM4(r, a) \
    asm volatile("ldmatrix.sync.aligned.m8n8.x4.shared.b16 {%0,%1,%2,%3}, [%4];" \
                 : "=r"((r)[0]), "=r"((r)[1]), "=r"((r)[2]), "=r"((r)[3]) : "r"(a))

__device__ __forceinline__ void mma_f16(float* d, const uint32_t* a,
                                        uint32_t b0, uint32_t b1) {
    asm volatile(
        "mma.sync.aligned.m16n8k16.row.col.f32.f16.f16.f32 "
        "{%0,%1,%2,%3}, {%4,%5,%6,%7}, {%8,%9}, {%0,%1,%2,%3};"
        : "+f"(d[0]), "+f"(d[1]), "+f"(d[2]), "+f"(d[3])
        : "r"(a[0]), "r"(a[1]), "r"(a[2]), "r"(a[3]), "r"(b0), "r"(b1));
}

__device__ __forceinline__ uint32_t hpack(float a, float b) {
    const __half2 h = __floats2half2_rn(a, b);
    return *(const uint32_t*)&h;
}

// ---------------- kernel: LN stats + gate weights + norm(x)->fp16 -------------
__global__ void k_gate(const float* __restrict__ x, const int* __restrict__ dm,
                       const float* __restrict__ gw1, const float* __restrict__ gb1,
                       const float* __restrict__ gw2, const float* __restrict__ gb2) {
    const int t = blockIdx.x * 8 + (threadIdx.x >> 5);
    const int lane = threadIdx.x & 31;
    const float* xr = x + (size_t)t * Hd;

    float4 xv[8];
    float s = 0.f, ss = 0.f, a0 = 0.f, a1 = 0.f, a2 = 0.f, a3 = 0.f;
    #pragma unroll
    for (int it = 0; it < 8; it++) {
        const int h = lane * 4 + it * 128;
        xv[it] = *(const float4*)(xr + h);
        const float4 v = xv[it];
        s  += v.x + v.y + v.z + v.w;
        ss += v.x * v.x + v.y * v.y + v.z * v.z + v.w * v.w;
        const float4* gw = (const float4*)(gw1 + h * 4);
        float4 w0r = gw[0], w1r = gw[1], w2r = gw[2], w3r = gw[3];
        a0 += v.x * w0r.x + v.y * w1r.x + v.z * w2r.x + v.w * w3r.x;
        a1 += v.x * w0r.y + v.y * w1r.y + v.z * w2r.y + v.w * w3r.y;
        a2 += v.x * w0r.z + v.y * w1r.z + v.z * w2r.z + v.w * w3r.z;
        a3 += v.x * w0r.w + v.y * w1r.w + v.z * w2r.w + v.w * w3r.w;
    }
    #pragma unroll
    for (int o = 16; o; o >>= 1) {
        s  += __shfl_xor_sync(0xffffffffu, s, o);
        ss += __shfl_xor_sync(0xffffffffu, ss, o);
        a0 += __shfl_xor_sync(0xffffffffu, a0, o);
        a1 += __shfl_xor_sync(0xffffffffu, a1, o);
        a2 += __shfl_xor_sync(0xffffffffu, a2, o);
        a3 += __shfl_xor_sync(0xffffffffu, a3, o);
    }
    const float mean = s * (1.f / Hd);
    const float var = ss * (1.f / Hd) - mean * mean;
    const float rstd = rsqrtf(var + 1e-6f);

    #pragma unroll
    for (int it = 0; it < 8; it++) {
        const int h = lane * 4 + it * 128;
        const float4 v = xv[it];
        uint2 o;
        o.x = hpack((v.x - mean) * rstd, (v.y - mean) * rstd);
        o.y = hpack((v.z - mean) * rstd, (v.w - mean) * rstd);
        *(uint2*)(g_xh + (size_t)t * Hd + h) = o;
    }

    if (lane == 0) {
        float hv[4] = {fmaxf(a0 + gb1[0], 0.f), fmaxf(a1 + gb1[1], 0.f),
                       fmaxf(a2 + gb1[2], 0.f), fmaxf(a3 + gb1[3], 0.f)};
        float lg[4];
        #pragma unroll
        for (int e = 0; e < 4; e++) {
            float acc = gb2[e];
            #pragma unroll
            for (int d = 0; d < 4; d++) acc += hv[d] * gw2[d * 4 + e];
            if (dm[e] == 0) acc = -1e9f;
            lg[e] = acc;
        }
        const float mx = fmaxf(fmaxf(lg[0], lg[1]), fmaxf(lg[2], lg[3]));
        const float e0 = expf(lg[0] - mx), e1 = expf(lg[1] - mx);
        const float e2 = expf(lg[2] - mx), e3 = expf(lg[3] - mx);
        const float inv = 1.f / (e0 + e1 + e2 + e3);
        g_wts[4 * t + 0] = e0 * inv;
        g_wts[4 * t + 1] = e1 * inv;
        g_wts[4 * t + 2] = e2 * inv;
        g_wts[4 * t + 3] = (e1 + e2) * inv;
    }
}

// ---------------- kernel: transpose + scale W1 -> fp16, both domains ----------
__global__ void k_trans1(const float* __restrict__ w1, const float* __restrict__ sb,
                         const float* __restrict__ si) {
    __shared__ float t[32][33];
    const int tx = threadIdx.x, ty = threadIdx.y;
    const int f0 = blockIdx.x * 32, h0 = blockIdx.y * 32;
    #pragma unroll
    for (int i = 0; i < 4; i++) {
        const int h = h0 + ty + i * 8;
        t[ty + i * 8][tx] = w1[(size_t)h * Fd + f0 + tx];
    }
    __syncthreads();
    const int h = h0 + tx;
    const float s_b = sb[h], s_i = si[h];
    #pragma unroll
    for (int i = 0; i < 4; i++) {
        const int fo = f0 + ty + i * 8;
        const float w = t[tx][ty + i * 8];
        const size_t o = (size_t)fo * Hd + h;
        g_Bb[o] = __float2half_rn(w * s_b);
        g_Bi[o] = __float2half_rn(w * s_i);
    }
}

// ---------------- kernel: transpose W2 -> fp16 --------------------------------
__global__ void k_trans2(const float* __restrict__ w2) {
    __shared__ float t[32][33];
    const int tx = threadIdx.x, ty = threadIdx.y;
    const int h0 = blockIdx.x * 32, f0 = blockIdx.y * 32;
    #pragma unroll
    for (int i = 0; i < 4; i++) {
        const int f = f0 + ty + i * 8;
        t[ty + i * 8][tx] = w2[(size_t)f * Hd + h0 + tx];
    }
    __syncthreads();
    const int f = f0 + tx;
    #pragma unroll
    for (int i = 0; i < 4; i++) {
        const int ho = h0 + ty + i * 8;
        g_W2[(size_t)ho * Fd + f] = __float2half_rn(t[tx][ty + i * 8]);
    }
}

// ---------------- kernel: c_d = b_d @ W1 + ad_b1, split-K parallel ------------
__global__ void k_prepc(const float* __restrict__ w1, const float* __restrict__ bb,
                        const float* __restrict__ bi, const float* __restrict__ ab1) {
    __shared__ float red[8][32];
    const int lane32 = threadIdx.x & 31;
    const int ks = threadIdx.x >> 5;
    const int i = blockIdx.x * 32 + lane32;        // 0..4095
    const int d = i >> 11;
    const int f = i & (Fd - 1);
    const float* bv = d ? bi : bb;
    float acc = 0.f;
    #pragma unroll 8
    for (int h = ks * 128; h < ks * 128 + 128; h++)
        acc = fmaf(__ldg(bv + h), w1[(size_t)h * Fd + f], acc);
    red[ks][lane32] = acc;
    __syncthreads();
    if (ks == 0) {
        float s = red[0][lane32];
        #pragma unroll
        for (int q = 1; q < 8; q++) s += red[q][lane32];
        g_cvec[d][f] = ab1[f] + s;
    }
}

// ---------------- kernel: up GEMM, 256 thr, 2 CTAs/SM, fused gate-combine -----
// CTA 128m x 64f per domain. dom = wid>>2; within: 2m x 2n, warp 64m x 32f.
// Stage (16KB): A 128x32 (8K) | B_book 64x32 (4K) | B_iwslt 64x32 (4K); x4 = 64K.
#define UP_SMEM  65536
#define UP_STAGE 16384
__global__ void __launch_bounds__(256, 2) k_up() {
    extern __shared__ char smem[];
    const uint32_t sm = smem_u32(smem);
    const int tid = threadIdx.x, lane = tid & 31, wid = tid >> 5;
    const int m0 = blockIdx.y * 128, n0 = blockIdx.x * 64;
    const int dom = wid >> 2, wsub = wid & 3;
    const int mw = (wsub & 1) * 64, nw = (wsub >> 1) * 32;
    const int aRow = lane & 15, aK = lane >> 4;
    const int bRow = (lane & 7) + ((lane >> 4) << 3), bK = (lane >> 3) & 1;
    const __half* Bsrc[2] = {g_Bb, g_Bi};

    float acc[4][4][4];
    #pragma unroll
    for (int i = 0; i < 4; i++)
        #pragma unroll
        for (int n = 0; n < 4; n++)
            #pragma unroll
            for (int q = 0; q < 4; q++) acc[i][n][q] = 0.f;

    auto load = [&](int c) {
        const uint32_t sb = sm + (c & 3) * UP_STAGE;
        #pragma unroll
        for (int rep = 0; rep < 2; rep++) {   // A: 512 units [kb(4)][r(128)]
            const int idx = tid + rep * 256;
            const int r = idx & 127, kb = idx >> 7;
            CP16(sb + idx * 16, g_xh + (size_t)(m0 + r) * Hd + c * 32 + kb * 8);
        }
        #pragma unroll
        for (int rep = 0; rep < 2; rep++) {   // B: 2 dom x 256 units [kb(4)][f(64)]
            const int u = tid + rep * 256;
            const int d = u >> 8, within = u & 255;
            const int f = within & 63, kb = within >> 6;
            CP16(sb + 8192 + u * 16, Bsrc[d] + (size_t)(n0 + f) * Hd + c * 32 + kb * 8);
        }
        CP_COMMIT();
    };

    load(0); load(1); load(2);

    #pragma unroll 1
    for (int c = 0; c < 32; c++) {
        if (c < 29) CP_WAITG(2); else CP_WAITG(0);
        __syncthreads();
        if (c + 3 < 32) load(c + 3);
        const uint32_t smA = sm + (c & 3) * UP_STAGE;
        const uint32_t smB = smA + 8192 + dom * 4096;
        #pragma unroll
        for (int j = 0; j < 2; j++) {
            uint32_t a[4][4];
            const uint32_t aBase = smA + (((2 * j + aK) << 7) + mw + aRow) * 16;
            #pragma unroll
            for (int i = 0; i < 4; i++) LDSM4(a[i], aBase + i * 256);
            uint32_t b[2][4];
            const uint32_t bBase = smB + (((2 * j + bK) << 6) + nw + bRow) * 16;
            #pragma unroll
            for (int nb = 0; nb < 2; nb++) LDSM4(b[nb], bBase + nb * 256);
            #pragma unroll
            for (int i = 0; i < 4; i++)
                #pragma unroll
                for (int nb = 0; nb < 2; nb++) {
                    mma_f16(acc[i][2 * nb + 0], a[i], b[nb][0], b[nb][1]);
                    mma_f16(acc[i][2 * nb + 1], a[i], b[nb][2], b[nb][3]);
                }
        }
    }

    // --- epilogue: dom1 -> smem (w2*relu), dom0 combines, writes g fp16 -------
    __syncthreads();
    const int g = lane >> 2, tq = lane & 3;
    float* ex = (float*)smem;               // [128][68] f32 = 34.8KB
    if (dom == 1) {
        #pragma unroll
        for (int i = 0; i < 4; i++) {
            const int r = mw + 16 * i + g;
            const float w2a = g_wts[4 * (m0 + r) + 2];
            const float w2b = g_wts[4 * (m0 + r + 8) + 2];
            #pragma unroll
            for (int n = 0; n < 4; n++) {
                const int col = nw + 8 * n + 2 * tq;
                const float cv0 = g_cvec[1][n0 + col], cv1 = g_cvec[1][n0 + col + 1];
                float2 v0, v1;
                v0.x = w2a * fmaxf(acc[i][n][0] + cv0, 0.f);
                v0.y = w2a * fmaxf(acc[i][n][1] + cv1, 0.f);
                v1.x = w2b * fmaxf(acc[i][n][2] + cv0, 0.f);
                v1.y = w2b * fmaxf(acc[i][n][3] + cv1, 0.f);
                *(float2*)(ex + (size_t)r * 68 + col) = v0;
                *(float2*)(ex + (size_t)(r + 8) * 68 + col) = v1;
            }
        }
    }
    __syncthreads();
    if (dom == 0) {
        #pragma unroll
        for (int i = 0; i < 4; i++) {
            const int r = mw + 16 * i + g;
            const float w1a = g_wts[4 * (m0 + r) + 1];
            const float w1b = g_wts[4 * (m0 + r + 8) + 1];
            #pragma unroll
            for (int n = 0; n < 4; n++) {
                const int col = nw + 8 * n + 2 * tq;
                const float cv0 = g_cvec[0][n0 + col], cv1 = g_cvec[0][n0 + col + 1];
                const float2 s0 = *(const float2*)(ex + (size_t)r * 68 + col);
                const float2 s1 = *(const float2*)(ex + (size_t)(r + 8) * 68 + col);
                const float g0 = w1a * fmaxf(acc[i][n][0] + cv0, 0.f) + s0.x;
                const float g1 = w1a * fmaxf(acc[i][n][1] + cv1, 0.f) + s0.y;
                const float g2 = w1b * fmaxf(acc[i][n][2] + cv0, 0.f) + s1.x;
                const float g3 = w1b * fmaxf(acc[i][n][3] + cv1, 0.f) + s1.y;
                *(uint32_t*)(g_g + (size_t)(m0 + r) * Fd + n0 + col) = hpack(g0, g1);
                *(uint32_t*)(g_g + (size_t)(m0 + r + 8) * Fd + n0 + col) = hpack(g2, g3);
            }
        }
    }
}

// ---------------- kernel: down GEMM, 256 thr, 2 CTAs/SM + residual mix --------
// CTA 128m x 128h. 8 warps 2m x 4n, warp 64m x 32h.
// Stage (16KB): A 128x32 (8K) | B 128x32 (8K); x4 = 64K.
#define DN_SMEM  65536
#define DN_STAGE 16384
__global__ void __launch_bounds__(256, 2) k_down(const float* __restrict__ x,
                                                 const float* __restrict__ b2,
                                                 float* __restrict__ out) {
    extern __shared__ char smem[];
    const uint32_t sm = smem_u32(smem);
    const int tid = threadIdx.x, lane = tid & 31, wid = tid >> 5;
    const int m0 = blockIdx.y * 128, n0 = blockIdx.x * 128;
    const int mw = (wid & 1) * 64, nw = (wid >> 1) * 32;
    const int aRow = lane & 15, aK = lane >> 4;
    const int bRow = (lane & 7) + ((lane >> 4) << 3), bK = (lane >> 3) & 1;

    float acc[4][4][4];
    #pragma unroll
    for (int i = 0; i < 4; i++)
        #pragma unroll
        for (int n = 0; n < 4; n++)
            #pragma unroll
            for (int q = 0; q < 4; q++) acc[i][n][q] = 0.f;

    auto load = [&](int c) {
        const uint32_t sb = sm + (c & 3) * DN_STAGE;
        #pragma unroll
        for (int rep = 0; rep < 2; rep++) {   // A: 512 units [kb(4)][r(128)]
            const int idx = tid + rep * 256;
            const int r = idx & 127, kb = idx >> 7;
            CP16(sb + idx * 16, g_g + (size_t)(m0 + r) * Fd + c * 32 + kb * 8);
        }
        #pragma unroll
        for (int rep = 0; rep < 2; rep++) {   // B: 512 units [kb(4)][h(128)]
            const int u = tid + rep * 256;
            const int h = u & 127, kb = u >> 7;
            CP16(sb + 8192 + u * 16, g_W2 + (size_t)(n0 + h) * Fd + c * 32 + kb * 8);
        }
        CP_COMMIT();
    };

    load(0); load(1); load(2);

    #pragma unroll 1
    for (int c = 0; c < 64; c++) {
        if (c < 61) CP_WAITG(2); else CP_WAITG(0);
        __syncthreads();
        if (c + 3 < 64) load(c + 3);
        const uint32_t smA = sm + (c & 3) * DN_STAGE;
        const uint32_t smB = smA + 8192;
        #pragma unroll
        for (int j = 0; j < 2; j++) {
            uint32_t a[4][4];
            const uint32_t aBase = smA + (((2 * j + aK) << 7) + mw + aRow) * 16;
            #pragma unroll
            for (int i = 0; i < 4; i++) LDSM4(a[i], aBase + i * 256);
            uint32_t b[2][4];
            const uint32_t bBase = smB + (((2 * j + bK) << 7) + nw + bRow) * 16;
            #pragma unroll
            for (int nb = 0; nb < 2; nb++) LDSM4(b[nb], bBase + nb * 256);
            #pragma unroll
            for (int i = 0; i < 4; i++)
                #pragma unroll
                for (int nb = 0; nb < 2; nb++) {
                    mma_f16(acc[i][2 * nb + 0], a[i], b[nb][0], b[nb][1]);
                    mma_f16(acc[i][2 * nb + 1], a[i], b[nb][2], b[nb][3]);
                }
        }
    }

    // --- epilogue: out = x*(1+w0) + acc + (w1+w2)*b2 --------------------------
    const int g = lane >> 2, tq = lane & 3;
    #pragma unroll
    for (int i = 0; i < 4; i++) {
        const int r0 = m0 + mw + 16 * i + g;
        const float4 wv0 = *(const float4*)&g_wts[4 * r0];
        const float4 wv1 = *(const float4*)&g_wts[4 * (r0 + 8)];
        const float xs0 = 1.f + wv0.x, w120 = wv0.w;
        const float xs1 = 1.f + wv1.x, w121 = wv1.w;
        #pragma unroll
        for (int n = 0; n < 4; n++) {
            const int h = n0 + nw + 8 * n + 2 * tq;
            const float2 xa = *(const float2*)&x[(size_t)r0 * Hd + h];
            const float2 xb = *(const float2*)&x[(size_t)(r0 + 8) * Hd + h];
            const float2 bv = *(const float2*)&b2[h];
            float2 o0, o1;
            o0.x = xa.x * xs0 + acc[i][n][0] + w120 * bv.x;
            o0.y = xa.y * xs0 + acc[i][n][1] + w120 * bv.y;
            o1.x = xb.x * xs1 + acc[i][n][2] + w121 * bv.x;
            o1.y = xb.y * xs1 + acc[i][n][3] + w121 * bv.y;
            *(float2*)&out[(size_t)r0 * Hd + h] = o0;
            *(float2*)&out[(size_t)(r0 + 8) * Hd + h] = o1;
        }
    }
}

// ---------------- launch (order chosen so slot #4 = k_up for ncu) -------------
extern "C" void kernel_launch(void* const* d_in, const int* in_sizes, int n_in,
                              void* d_out, int out_size) {
    const float* x   = (const float*)d_in[0];
    const int*   dm  = (const int*)d_in[1];
    const float* gw1 = (const float*)d_in[2];
    const float* gb1 = (const float*)d_in[3];
    const float* gw2 = (const float*)d_in[4];
    const float* gb2 = (const float*)d_in[5];
    const float* sb  = (const float*)d_in[6];
    const float* bb  = (const float*)d_in[7];
    const float* si  = (const float*)d_in[8];
    const float* bi  = (const float*)d_in[9];
    const float* aw1 = (const float*)d_in[10];
    const float* ab1 = (const float*)d_in[11];
    const float* aw2 = (const float*)d_in[12];
    const float* ab2 = (const float*)d_in[13];
    float* out = (float*)d_out;

    cudaFuncSetAttribute(k_up, cudaFuncAttributeMaxDynamicSharedMemorySize, UP_SMEM);
    cudaFuncSetAttribute(k_down, cudaFuncAttributeMaxDynamicSharedMemorySize, DN_SMEM);

    k_trans1<<<dim3(Fd / 32, Hd / 32), dim3(32, 8)>>>(aw1, sb, si);   // #1
    k_prepc<<<(2 * Fd) / 32, 256>>>(aw1, bb, bi, ab1);                // #2
    k_gate<<<Td / 8, 256>>>(x, dm, gw1, gb1, gw2, gb2);               // #3
    k_up<<<dim3(Fd / 64, Td / 128), 256, UP_SMEM>>>();                // #4 (ncu)
    k_trans2<<<dim3(Hd / 32, Fd / 32), dim3(32, 8)>>>(aw2);           // #5
    k_down<<<dim3(Hd / 128, Td / 128), 256, DN_SMEM>>>(x, ab2, out);  // #6
}

// round 9
// speedup vs baseline: 1.8746x; 1.8746x over previous
#include <cuda_runtime.h>
#include <cuda_fp16.h>
#include <cstdint>

#define Hd 1024
#define Fd 2048
#define Td 8192

// ---------------- scratch (__device__ globals; no allocs allowed) -------------
__device__ __align__(16) float g_wts[Td * 4];    // w0, w1, w2, w1+w2
__device__ __align__(16) float g_cvec[2][Fd];    // b_d @ ad_w1 + ad_b1
// tile-packed operands (blocks laid out exactly as the GEMM smem stages):
//   xp : [mb(64)][c(32)][kb(4)][r(128)][8h]      norm(x) fp16, 8KB blocks
//   Bp : [dom(2)][nb(32)][c(32)][kb(4)][f(64)][8h]  W1^T scaled, 4KB blocks
//   W2p: [hb(8)][c(64)][kb(4)][h(128)][8h]       W2^T, 8KB blocks
//   gp : [mb(64)][c(64)][kb(4)][r(128)][8h]      combined act, 8KB blocks
__device__ __align__(16) __half g_xp[(size_t)Td * Hd];
__device__ __align__(16) __half g_Bp[2 * (size_t)Fd * Hd];
__device__ __align__(16) __half g_W2p[(size_t)Hd * Fd];
__device__ __align__(16) __half g_gp[(size_t)Td * Fd];

// ---------------- PTX helpers -------------------------------------------------
__device__ __forceinline__ uint32_t smem_u32(const void* p) {
    uint32_t a;
    asm("{ .reg .u64 t; cvta.to.shared.u64 t, %1; cvt.u32.u64 %0, t; }"
        : "=r"(a) : "l"(p));
    return a;
}
#define LDSM4(r, a) \
    asm volatile("ldmatrix.sync.aligned.m8n8.x4.shared.b16 {%0,%1,%2,%3}, [%4];" \
                 : "=r"((r)[0]), "=r"((r)[1]), "=r"((r)[2]), "=r"((r)[3]) : "r"(a))
#define MBAR_INIT(a, c)  asm volatile("mbarrier.init.shared.b64 [%0], %1;" :: "r"(a), "r"((uint32_t)(c)) : "memory")
#define MBAR_EXPECT(a, tx) asm volatile("mbarrier.arrive.expect_tx.shared.b64 _, [%0], %1;" :: "r"(a), "r"((uint32_t)(tx)) : "memory")
#define MBAR_WAIT(a, p) do { \
    uint32_t _m = (a), _p = (uint32_t)(p), _d; \
    asm volatile("{\n\t.reg .pred q;\n\tmbarrier.try_wait.parity.acquire.cta.shared::cta.b64 q, [%1], %2;\n\tselp.b32 %0,1,0,q;\n\t}" \
                 : "=r"(_d) : "r"(_m), "r"(_p) : "memory"); \
    if (!_d) { \
        asm volatile("{\n\t.reg .pred q;\n\tLW_%=:\n\tmbarrier.try_wait.parity.acquire.cta.shared::cta.b64 q, [%0], %1, 0x989680;\n\t@q bra.uni LD_%=;\n\tbra.uni LW_%=;\n\tLD_%=:\n\t}" \
                     :: "r"(_m), "r"(_p) : "memory"); \
    } } while (0)
#define BULK(dst, src, sz, mb) \
    asm volatile("cp.async.bulk.shared::cluster.global.mbarrier::complete_tx::bytes [%0], [%1], %2, [%3];" \
                 :: "r"(dst), "l"(__cvta_generic_to_global(src)), "r"((uint32_t)(sz)), "r"(mb) : "memory")

__device__ __forceinline__ void mma_f16(float* d, const uint32_t* a,
                                        uint32_t b0, uint32_t b1) {
    asm volatile(
        "mma.sync.aligned.m16n8k16.row.col.f32.f16.f16.f32 "
        "{%0,%1,%2,%3}, {%4,%5,%6,%7}, {%8,%9}, {%0,%1,%2,%3};"
        : "+f"(d[0]), "+f"(d[1]), "+f"(d[2]), "+f"(d[3])
        : "r"(a[0]), "r"(a[1]), "r"(a[2]), "r"(a[3]), "r"(b0), "r"(b1));
}

__device__ __forceinline__ uint32_t hpack(float a, float b) {
    const __half2 h = __floats2half2_rn(a, b);
    return *(const uint32_t*)&h;
}
__device__ __forceinline__ size_t gp_off(int m, int f) {   // halves offset in g_gp
    return ((size_t)((m >> 7) * 64 + (f >> 5))) * 4096 +
           ((f >> 3) & 3) * 1024 + (m & 127) * 8 + (f & 7);
}

// ---------------- kernel: LN stats + gate weights + packed norm(x) ------------
__global__ void k_gate(const float* __restrict__ x, const int* __restrict__ dm,
                       const float* __restrict__ gw1, const float* __restrict__ gb1,
                       const float* __restrict__ gw2, const float* __restrict__ gb2) {
    const int t = blockIdx.x * 8 + (threadIdx.x >> 5);
    const int lane = threadIdx.x & 31;
    const float* xr = x + (size_t)t * Hd;

    float4 xv[8];
    float s = 0.f, ss = 0.f, a0 = 0.f, a1 = 0.f, a2 = 0.f, a3 = 0.f;
    #pragma unroll
    for (int it = 0; it < 8; it++) {
        const int h = lane * 4 + it * 128;
        xv[it] = *(const float4*)(xr + h);
        const float4 v = xv[it];
        s  += v.x + v.y + v.z + v.w;
        ss += v.x * v.x + v.y * v.y + v.z * v.z + v.w * v.w;
        const float4* gw = (const float4*)(gw1 + h * 4);
        float4 w0r = gw[0], w1r = gw[1], w2r = gw[2], w3r = gw[3];
        a0 += v.x * w0r.x + v.y * w1r.x + v.z * w2r.x + v.w * w3r.x;
        a1 += v.x * w0r.y + v.y * w1r.y + v.z * w2r.y + v.w * w3r.y;
        a2 += v.x * w0r.z + v.y * w1r.z + v.z * w2r.z + v.w * w3r.z;
        a3 += v.x * w0r.w + v.y * w1r.w + v.z * w2r.w + v.w * w3r.w;
    }
    #pragma unroll
    for (int o = 16; o; o >>= 1) {
        s  += __shfl_xor_sync(0xffffffffu, s, o);
        ss += __shfl_xor_sync(0xffffffffu, ss, o);
        a0 += __shfl_xor_sync(0xffffffffu, a0, o);
        a1 += __shfl_xor_sync(0xffffffffu, a1, o);
        a2 += __shfl_xor_sync(0xffffffffu, a2, o);
        a3 += __shfl_xor_sync(0xffffffffu, a3, o);
    }
    const float mean = s * (1.f / Hd);
    const float var = ss * (1.f / Hd) - mean * mean;
    const float rstd = rsqrtf(var + 1e-6f);

    const int mb = t >> 7, r = t & 127;
    #pragma unroll
    for (int it = 0; it < 8; it++) {
        const int k = lane * 4 + it * 128;
        const int c = k >> 5, kb = (k >> 3) & 3, wi = k & 7;
        const float4 v = xv[it];
        uint2 o;
        o.x = hpack((v.x - mean) * rstd, (v.y - mean) * rstd);
        o.y = hpack((v.z - mean) * rstd, (v.w - mean) * rstd);
        *(uint2*)(g_xp + ((size_t)(mb * 32 + c)) * 4096 + kb * 1024 + r * 8 + wi) = o;
    }

    if (lane == 0) {
        float hv[4] = {fmaxf(a0 + gb1[0], 0.f), fmaxf(a1 + gb1[1], 0.f),
                       fmaxf(a2 + gb1[2], 0.f), fmaxf(a3 + gb1[3], 0.f)};
        float lg[4];
        #pragma unroll
        for (int e = 0; e < 4; e++) {
            float acc = gb2[e];
            #pragma unroll
            for (int d = 0; d < 4; d++) acc += hv[d] * gw2[d * 4 + e];
            if (dm[e] == 0) acc = -1e9f;
            lg[e] = acc;
        }
        const float mx = fmaxf(fmaxf(lg[0], lg[1]), fmaxf(lg[2], lg[3]));
        const float e0 = expf(lg[0] - mx), e1 = expf(lg[1] - mx);
        const float e2 = expf(lg[2] - mx), e3 = expf(lg[3] - mx);
        const float inv = 1.f / (e0 + e1 + e2 + e3);
        g_wts[4 * t + 0] = e0 * inv;
        g_wts[4 * t + 1] = e1 * inv;
        g_wts[4 * t + 2] = e2 * inv;
        g_wts[4 * t + 3] = (e1 + e2) * inv;
    }
}

// ---------------- kernel: transpose + scale W1 -> packed fp16, both domains ---
__global__ void k_trans1(const float* __restrict__ w1, const float* __restrict__ sb,
                         const float* __restrict__ si) {
    __shared__ float t[32][33];
    const int tx = threadIdx.x, ty = threadIdx.y;
    const int f0 = blockIdx.x * 32, h0 = blockIdx.y * 32;
    #pragma unroll
    for (int i = 0; i < 4; i++) {
        const int h = h0 + ty + i * 8;
        t[ty + i * 8][tx] = w1[(size_t)h * Fd + f0 + tx];
    }
    __syncthreads();
    const int h = h0 + tx;
    const float s_b = sb[h], s_i = si[h];
    const int c = h >> 5, kb = (h >> 3) & 3, wi = h & 7;
    #pragma unroll
    for (int i = 0; i < 4; i++) {
        const int fo = f0 + ty + i * 8;
        const float w = t[tx][ty + i * 8];
        const size_t off = ((size_t)((fo >> 6) * 32 + c)) * 2048 +
                           kb * 512 + (fo & 63) * 8 + wi;
        g_Bp[off] = __float2half_rn(w * s_b);
        g_Bp[(size_t)Fd * Hd + off] = __float2half_rn(w * s_i);
    }
}

// ---------------- kernel: transpose W2 -> packed fp16 -------------------------
__global__ void k_trans2(const float* __restrict__ w2) {
    __shared__ float t[32][33];
    const int tx = threadIdx.x, ty = threadIdx.y;
    const int h0 = blockIdx.x * 32, f0 = blockIdx.y * 32;
    #pragma unroll
    for (int i = 0; i < 4; i++) {
        const int f = f0 + ty + i * 8;
        t[ty + i * 8][tx] = w2[(size_t)f * Hd + h0 + tx];
    }
    __syncthreads();
    const int f = f0 + tx;
    const int c = f >> 5, kb = (f >> 3) & 3, wi = f & 7;
    #pragma unroll
    for (int i = 0; i < 4; i++) {
        const int ho = h0 + ty + i * 8;
        const size_t off = ((size_t)((ho >> 7) * 64 + c)) * 4096 +
                           kb * 1024 + (ho & 127) * 8 + wi;
        g_W2p[off] = __float2half_rn(t[tx][ty + i * 8]);
    }
}

// ---------------- kernel: c_d = b_d @ W1 + ad_b1, split-K parallel ------------
__global__ void k_prepc(const float* __restrict__ w1, const float* __restrict__ bb,
                        const float* __restrict__ bi, const float* __restrict__ ab1) {
    __shared__ float red[8][32];
    const int lane32 = threadIdx.x & 31;
    const int ks = threadIdx.x >> 5;
    const int i = blockIdx.x * 32 + lane32;        // 0..4095
    const int d = i >> 11;
    const int f = i & (Fd - 1);
    const float* bv = d ? bi : bb;
    float acc = 0.f;
    #pragma unroll 8
    for (int h = ks * 128; h < ks * 128 + 128; h++)
        acc = fmaf(__ldg(bv + h), w1[(size_t)h * Fd + f], acc);
    red[ks][lane32] = acc;
    __syncthreads();
    if (ks == 0) {
        float s = red[0][lane32];
        #pragma unroll
        for (int q = 1; q < 8; q++) s += red[q][lane32];
        g_cvec[d][f] = ab1[f] + s;
    }
}

// ---------------- kernel: up GEMM (TMA bulk), fused gate-combine --------------
// CTA 128m x 64f per domain. dom = wid>>2; within: 2m x 2n, warp 64m x 32f.
// Stage (16KB): A 8K | B_book 4K | B_iwslt 4K; x4 stages + mbarriers at 65536.
#define UP_SMEM  65600
#define UP_STAGE 16384
__global__ void __launch_bounds__(256, 2) k_up() {
    extern __shared__ char smem[];
    const uint32_t sm = smem_u32(smem);
    const uint32_t mbb = sm + 65536;
    const int tid = threadIdx.x, lane = tid & 31, wid = tid >> 5;
    const int mb = blockIdx.y, nb = blockIdx.x;
    const int m0 = mb * 128, n0 = nb * 64;
    const int dom = wid >> 2, wsub = wid & 3;
    const int mw = (wsub & 1) * 64, nw = (wsub >> 1) * 32;
    const int aRow = lane & 15, aK = lane >> 4;
    const int bRow = (lane & 7) + ((lane >> 4) << 3), bK = (lane >> 3) & 1;

    float acc[4][4][4];
    #pragma unroll
    for (int i = 0; i < 4; i++)
        #pragma unroll
        for (int n = 0; n < 4; n++)
            #pragma unroll
            for (int q = 0; q < 4; q++) acc[i][n][q] = 0.f;

    auto issue = [&](int c) {
        const int s = c & 3;
        const uint32_t mbar = mbb + s * 8;
        const uint32_t dst = sm + s * UP_STAGE;
        MBAR_EXPECT(mbar, 16384);
        BULK(dst, g_xp + ((size_t)(mb * 32 + c)) * 4096, 8192, mbar);
        BULK(dst + 8192, g_Bp + ((size_t)(nb * 32 + c)) * 2048, 4096, mbar);
        BULK(dst + 12288, g_Bp + (size_t)Fd * Hd + ((size_t)(nb * 32 + c)) * 2048, 4096, mbar);
    };

    if (tid == 0) {
        #pragma unroll
        for (int s = 0; s < 4; s++) MBAR_INIT(mbb + s * 8, 1);
    }
    __syncthreads();
    if (tid == 0) { issue(0); issue(1); issue(2); }

    #pragma unroll 1
    for (int c = 0; c < 32; c++) {
        __syncthreads();                         // stage (c+3)&3 free for reuse
        if (tid == 0 && c + 3 < 32) issue(c + 3);
        MBAR_WAIT(mbb + (c & 3) * 8, (c >> 2) & 1);
        const uint32_t smA = sm + (c & 3) * UP_STAGE;
        const uint32_t smB = smA + 8192 + dom * 4096;
        #pragma unroll
        for (int j = 0; j < 2; j++) {
            uint32_t a[4][4];
            const uint32_t aBase = smA + (((2 * j + aK) << 7) + mw + aRow) * 16;
            #pragma unroll
            for (int i = 0; i < 4; i++) LDSM4(a[i], aBase + i * 256);
            uint32_t b[2][4];
            const uint32_t bBase = smB + (((2 * j + bK) << 6) + nw + bRow) * 16;
            #pragma unroll
            for (int nbb = 0; nbb < 2; nbb++) LDSM4(b[nbb], bBase + nbb * 256);
            #pragma unroll
            for (int i = 0; i < 4; i++)
                #pragma unroll
                for (int nbb = 0; nbb < 2; nbb++) {
                    mma_f16(acc[i][2 * nbb + 0], a[i], b[nbb][0], b[nbb][1]);
                    mma_f16(acc[i][2 * nbb + 1], a[i], b[nbb][2], b[nbb][3]);
                }
        }
    }

    // --- epilogue: dom1 -> smem (w2*relu), dom0 combines, writes packed g -----
    __syncthreads();
    const int g = lane >> 2, tq = lane & 3;
    float* ex = (float*)smem;               // [128][68] f32 = 34.8KB
    if (dom == 1) {
        #pragma unroll
        for (int i = 0; i < 4; i++) {
            const int r = mw + 16 * i + g;
            const float w2a = g_wts[4 * (m0 + r) + 2];
            const float w2b = g_wts[4 * (m0 + r + 8) + 2];
            #pragma unroll
            for (int n = 0; n < 4; n++) {
                const int col = nw + 8 * n + 2 * tq;
                const float cv0 = g_cvec[1][n0 + col], cv1 = g_cvec[1][n0 + col + 1];
                float2 v0, v1;
                v0.x = w2a * fmaxf(acc[i][n][0] + cv0, 0.f);
                v0.y = w2a * fmaxf(acc[i][n][1] + cv1, 0.f);
                v1.x = w2b * fmaxf(acc[i][n][2] + cv0, 0.f);
                v1.y = w2b * fmaxf(acc[i][n][3] + cv1, 0.f);
                *(float2*)(ex + (size_t)r * 68 + col) = v0;
                *(float2*)(ex + (size_t)(r + 8) * 68 + col) = v1;
            }
        }
    }
    __syncthreads();
    if (dom == 0) {
        #pragma unroll
        for (int i = 0; i < 4; i++) {
            const int r = mw + 16 * i + g;
            const float w1a = g_wts[4 * (m0 + r) + 1];
            const float w1b = g_wts[4 * (m0 + r + 8) + 1];
            #pragma unroll
            for (int n = 0; n < 4; n++) {
                const int col = nw + 8 * n + 2 * tq;
                const int fg = n0 + col;
                const float cv0 = g_cvec[0][fg], cv1 = g_cvec[0][fg + 1];
                const float2 s0 = *(const float2*)(ex + (size_t)r * 68 + col);
                const float2 s1 = *(const float2*)(ex + (size_t)(r + 8) * 68 + col);
                const float g0 = w1a * fmaxf(acc[i][n][0] + cv0, 0.f) + s0.x;
                const float g1 = w1a * fmaxf(acc[i][n][1] + cv1, 0.f) + s0.y;
                const float g2 = w1b * fmaxf(acc[i][n][2] + cv0, 0.f) + s1.x;
                const float g3 = w1b * fmaxf(acc[i][n][3] + cv1, 0.f) + s1.y;
                *(uint32_t*)(g_gp + gp_off(m0 + r, fg)) = hpack(g0, g1);
                *(uint32_t*)(g_gp + gp_off(m0 + r + 8, fg)) = hpack(g2, g3);
            }
        }
    }
}

// ---------------- kernel: down GEMM (TMA bulk) + residual + gated mix ---------
// CTA 128m x 128h. 8 warps 2m x 4n, warp 64m x 32h.
// Stage (16KB): A 8K | B 8K; x4 stages + mbarriers at 65536.
#define DN_SMEM  65600
#define DN_STAGE 16384
__global__ void __launch_bounds__(256, 2) k_down(const float* __restrict__ x,
                                                 const float* __restrict__ b2,
                                                 float* __restrict__ out) {
    extern __shared__ char smem[];
    const uint32_t sm = smem_u32(smem);
    const uint32_t mbb = sm + 65536;
    const int tid = threadIdx.x, lane = tid & 31, wid = tid >> 5;
    const int mb = blockIdx.y, hb = blockIdx.x;
    const int m0 = mb * 128, n0 = hb * 128;
    const int mw = (wid & 1) * 64, nw = (wid >> 1) * 32;
    const int aRow = lane & 15, aK = lane >> 4;
    const int bRow = (lane & 7) + ((lane >> 4) << 3), bK = (lane >> 3) & 1;

    float acc[4][4][4];
    #pragma unroll
    for (int i = 0; i < 4; i++)
        #pragma unroll
        for (int n = 0; n < 4; n++)
            #pragma unroll
            for (int q = 0; q < 4; q++) acc[i][n][q] = 0.f;

    auto issue = [&](int c) {
        const int s = c & 3;
        const uint32_t mbar = mbb + s * 8;
        const uint32_t dst = sm + s * DN_STAGE;
        MBAR_EXPECT(mbar, 16384);
        BULK(dst, g_gp + ((size_t)(mb * 64 + c)) * 4096, 8192, mbar);
        BULK(dst + 8192, g_W2p + ((size_t)(hb * 64 + c)) * 4096, 8192, mbar);
    };

    if (tid == 0) {
        #pragma unroll
        for (int s = 0; s < 4; s++) MBAR_INIT(mbb + s * 8, 1);
    }
    __syncthreads();
    if (tid == 0) { issue(0); issue(1); issue(2); }

    #pragma unroll 1
    for (int c = 0; c < 64; c++) {
        __syncthreads();
        if (tid == 0 && c + 3 < 64) issue(c + 3);
        MBAR_WAIT(mbb + (c & 3) * 8, (c >> 2) & 1);
        const uint32_t smA = sm + (c & 3) * DN_STAGE;
        const uint32_t smB = smA + 8192;
        #pragma unroll
        for (int j = 0; j < 2; j++) {
            uint32_t a[4][4];
            const uint32_t aBase = smA + (((2 * j + aK) << 7) + mw + aRow) * 16;
            #pragma unroll
            for (int i = 0; i < 4; i++) LDSM4(a[i], aBase + i * 256);
            uint32_t b[2][4];
            const uint32_t bBase = smB + (((2 * j + bK) << 7) + nw + bRow) * 16;
            #pragma unroll
            for (int nbb = 0; nbb < 2; nbb++) LDSM4(b[nbb], bBase + nbb * 256);
            #pragma unroll
            for (int i = 0; i < 4; i++)
                #pragma unroll
                for (int nbb = 0; nbb < 2; nbb++) {
                    mma_f16(acc[i][2 * nbb + 0], a[i], b[nbb][0], b[nbb][1]);
                    mma_f16(acc[i][2 * nbb + 1], a[i], b[nbb][2], b[nbb][3]);
                }
        }
    }

    // --- epilogue: out = x*(1+w0) + acc + (w1+w2)*b2 --------------------------
    const int g = lane >> 2, tq = lane & 3;
    #pragma unroll
    for (int i = 0; i < 4; i++) {
        const int r0 = m0 + mw + 16 * i + g;
        const float4 wv0 = *(const float4*)&g_wts[4 * r0];
        const float4 wv1 = *(const float4*)&g_wts[4 * (r0 + 8)];
        const float xs0 = 1.f + wv0.x, w120 = wv0.w;
        const float xs1 = 1.f + wv1.x, w121 = wv1.w;
        #pragma unroll
        for (int n = 0; n < 4; n++) {
            const int h = n0 + nw + 8 * n + 2 * tq;
            const float2 xa = *(const float2*)&x[(size_t)r0 * Hd + h];
            const float2 xb = *(const float2*)&x[(size_t)(r0 + 8) * Hd + h];
            const float2 bv = *(const float2*)&b2[h];
            float2 o0, o1;
            o0.x = xa.x * xs0 + acc[i][n][0] + w120 * bv.x;
            o0.y = xa.y * xs0 + acc[i][n][1] + w120 * bv.y;
            o1.x = xb.x * xs1 + acc[i][n][2] + w121 * bv.x;
            o1.y = xb.y * xs1 + acc[i][n][3] + w121 * bv.y;
            *(float2*)&out[(size_t)r0 * Hd + h] = o0;
            *(float2*)&out[(size_t)(r0 + 8) * Hd + h] = o1;
        }
    }
}

// ---------------- launch (order chosen so slot #4 = k_up for ncu) -------------
extern "C" void kernel_launch(void* const* d_in, const int* in_sizes, int n_in,
                              void* d_out, int out_size) {
    const float* x   = (const float*)d_in[0];
    const int*   dm  = (const int*)d_in[1];
    const float* gw1 = (const float*)d_in[2];
    const float* gb1 = (const float*)d_in[3];
    const float* gw2 = (const float*)d_in[4];
    const float* gb2 = (const float*)d_in[5];
    const float* sb  = (const float*)d_in[6];
    const float* bb  = (const float*)d_in[7];
    const float* si  = (const float*)d_in[8];
    const float* bi  = (const float*)d_in[9];
    const float* aw1 = (const float*)d_in[10];
    const float* ab1 = (const float*)d_in[11];
    const float* aw2 = (const float*)d_in[12];
    const float* ab2 = (const float*)d_in[13];
    float* out = (float*)d_out;

    cudaFuncSetAttribute(k_up, cudaFuncAttributeMaxDynamicSharedMemorySize, UP_SMEM);
    cudaFuncSetAttribute(k_down, cudaFuncAttributeMaxDynamicSharedMemorySize, DN_SMEM);

    k_trans1<<<dim3(Fd / 32, Hd / 32), dim3(32, 8)>>>(aw1, sb, si);   // #1
    k_prepc<<<(2 * Fd) / 32, 256>>>(aw1, bb, bi, ab1);                // #2
    k_gate<<<Td / 8, 256>>>(x, dm, gw1, gb1, gw2, gb2);               // #3
    k_up<<<dim3(Fd / 64, Td / 128), 256, UP_SMEM>>>();                // #4 (ncu)
    k_trans2<<<dim3(Hd / 32, Fd / 32), dim3(32, 8)>>>(aw2);           // #5
    k_down<<<dim3(Hd / 128, Td / 128), 256, DN_SMEM>>>(x, ab2, out);  // #6
}

// round 10
// speedup vs baseline: 1.9992x; 1.0665x over previous
#include <cuda_runtime.h>
#include <cuda_fp16.h>
#include <cstdint>

#define Hd 1024
#define Fd 2048
#define Td 8192

// ---------------- scratch (__device__ globals; no allocs allowed) -------------
__device__ __align__(16) float g_wts[Td * 4];    // w0, w1, w2, w1+w2
__device__ __align__(16) float g_cvec[2][Fd];    // b_d @ ad_w1 + ad_b1
// tile-packed operands (blocks laid out exactly as the GEMM smem stages):
//   xp : [mb(64)][c(32)][kb(4)][r(128)][8h]      norm(x) fp16, 8KB blocks
//   Bp : [dom(2)][nb(32)][c(32)][kb(4)][f(64)][8h]  W1^T scaled, 4KB blocks
//   W2p: [hb(8)][c(64)][kb(4)][h(128)][8h]       W2^T, 8KB blocks
//   gp : [mb(64)][c(64)][kb(4)][r(128)][8h]      combined act, 8KB blocks
__device__ __align__(16) __half g_xp[(size_t)Td * Hd];
__device__ __align__(16) __half g_Bp[2 * (size_t)Fd * Hd];
__device__ __align__(16) __half g_W2p[(size_t)Hd * Fd];
__device__ __align__(16) __half g_gp[(size_t)Td * Fd];

// ---------------- PTX helpers -------------------------------------------------
__device__ __forceinline__ uint32_t smem_u32(const void* p) {
    uint32_t a;
    asm("{ .reg .u64 t; cvta.to.shared.u64 t, %1; cvt.u32.u64 %0, t; }"
        : "=r"(a) : "l"(p));
    return a;
}
#define LDSM4(r, a) \
    asm volatile("ldmatrix.sync.aligned.m8n8.x4.shared.b16 {%0,%1,%2,%3}, [%4];" \
                 : "=r"((r)[0]), "=r"((r)[1]), "=r"((r)[2]), "=r"((r)[3]) : "r"(a))
#define MBAR_INIT(a, c)  asm volatile("mbarrier.init.shared.b64 [%0], %1;" :: "r"(a), "r"((uint32_t)(c)) : "memory")
#define MBAR_EXPECT(a, tx) asm volatile("mbarrier.arrive.expect_tx.shared.b64 _, [%0], %1;" :: "r"(a), "r"((uint32_t)(tx)) : "memory")
#define MBAR_WAIT(a, p) do { \
    uint32_t _m = (a), _p = (uint32_t)(p), _d; \
    asm volatile("{\n\t.reg .pred q;\n\tmbarrier.try_wait.parity.acquire.cta.shared::cta.b64 q, [%1], %2;\n\tselp.b32 %0,1,0,q;\n\t}" \
                 : "=r"(_d) : "r"(_m), "r"(_p) : "memory"); \
    if (!_d) { \
        asm volatile("{\n\t.reg .pred q;\n\tLW_%=:\n\tmbarrier.try_wait.parity.acquire.cta.shared::cta.b64 q, [%0], %1, 0x989680;\n\t@q bra.uni LD_%=;\n\tbra.uni LW_%=;\n\tLD_%=:\n\t}" \
                     :: "r"(_m), "r"(_p) : "memory"); \
    } } while (0)
#define BULK(dst, src, sz, mb) \
    asm volatile("cp.async.bulk.shared::cluster.global.mbarrier::complete_tx::bytes [%0], [%1], %2, [%3];" \
                 :: "r"(dst), "l"(__cvta_generic_to_global(src)), "r"((uint32_t)(sz)), "r"(mb) : "memory")

__device__ __forceinline__ void mma_f16(float* d, const uint32_t* a,
                                        uint32_t b0, uint32_t b1) {
    asm volatile(
        "mma.sync.aligned.m16n8k16.row.col.f32.f16.f16.f32 "
        "{%0,%1,%2,%3}, {%4,%5,%6,%7}, {%8,%9}, {%0,%1,%2,%3};"
        : "+f"(d[0]), "+f"(d[1]), "+f"(d[2]), "+f"(d[3])
        : "r"(a[0]), "r"(a[1]), "r"(a[2]), "r"(a[3]), "r"(b0), "r"(b1));
}

__device__ __forceinline__ uint32_t hpack(float a, float b) {
    const __half2 h = __floats2half2_rn(a, b);
    return *(const uint32_t*)&h;
}
__device__ __forceinline__ size_t gp_off(int m, int f) {   // halves offset in g_gp
    return ((size_t)((m >> 7) * 64 + (f >> 5))) * 4096 +
           ((f >> 3) & 3) * 1024 + (m & 127) * 8 + (f & 7);
}

// ---------------- fused prep: trans1 | trans2 | prepc | gate ------------------
// block ranges: [0,2048) trans1, [2048,4096) trans2, [4096,4224) prepc,
//               [4224,5248) gate. All 256 threads.
__global__ void k_prep(const float* __restrict__ x, const int* __restrict__ dm,
                       const float* __restrict__ gw1, const float* __restrict__ gb1,
                       const float* __restrict__ gw2, const float* __restrict__ gb2,
                       const float* __restrict__ sb, const float* __restrict__ si,
                       const float* __restrict__ bb, const float* __restrict__ bi,
                       const float* __restrict__ aw1, const float* __restrict__ ab1,
                       const float* __restrict__ aw2) {
    __shared__ float sh[32 * 33];
    const int b = blockIdx.x;
    const int tid = threadIdx.x;

    if (b < 2048) {                    // ---- trans1: W1 -> packed, 2 domains
        const int tx = tid & 31, ty = tid >> 5;
        const int f0 = (b & 63) * 32, h0 = (b >> 6) * 32;
        #pragma unroll
        for (int i = 0; i < 4; i++) {
            const int h = h0 + ty + i * 8;
            sh[(ty + i * 8) * 33 + tx] = aw1[(size_t)h * Fd + f0 + tx];
        }
        __syncthreads();
        const int h = h0 + tx;
        const float s_b = sb[h], s_i = si[h];
        const int c = h >> 5, kb = (h >> 3) & 3, wi = h & 7;
        #pragma unroll
        for (int i = 0; i < 4; i++) {
            const int fo = f0 + ty + i * 8;
            const float w = sh[tx * 33 + ty + i * 8];
            const size_t off = ((size_t)((fo >> 6) * 32 + c)) * 2048 +
                               kb * 512 + (fo & 63) * 8 + wi;
            g_Bp[off] = __float2half_rn(w * s_b);
            g_Bp[(size_t)Fd * Hd + off] = __float2half_rn(w * s_i);
        }
    } else if (b < 4096) {             // ---- trans2: W2 -> packed
        const int bb2 = b - 2048;
        const int tx = tid & 31, ty = tid >> 5;
        const int h0 = (bb2 & 31) * 32, f0 = (bb2 >> 5) * 32;
        #pragma unroll
        for (int i = 0; i < 4; i++) {
            const int f = f0 + ty + i * 8;
            sh[(ty + i * 8) * 33 + tx] = aw2[(size_t)f * Hd + h0 + tx];
        }
        __syncthreads();
        const int f = f0 + tx;
        const int c = f >> 5, kb = (f >> 3) & 3, wi = f & 7;
        #pragma unroll
        for (int i = 0; i < 4; i++) {
            const int ho = h0 + ty + i * 8;
            const size_t off = ((size_t)((ho >> 7) * 64 + c)) * 4096 +
                               kb * 1024 + (ho & 127) * 8 + wi;
            g_W2p[off] = __float2half_rn(sh[tx * 33 + ty + i * 8]);
        }
    } else if (b < 4224) {             // ---- prepc: c_d = b_d @ W1 + ad_b1
        const int lane32 = tid & 31;
        const int ks = tid >> 5;
        const int i = (b - 4096) * 32 + lane32;
        const int d = i >> 11;
        const int f = i & (Fd - 1);
        const float* bv = d ? bi : bb;
        float acc = 0.f;
        #pragma unroll 8
        for (int h = ks * 128; h < ks * 128 + 128; h++)
            acc = fmaf(__ldg(bv + h), aw1[(size_t)h * Fd + f], acc);
        sh[ks * 32 + lane32] = acc;
        __syncthreads();
        if (ks == 0) {
            float s = sh[lane32];
            #pragma unroll
            for (int q = 1; q < 8; q++) s += sh[q * 32 + lane32];
            g_cvec[d][f] = ab1[f] + s;
        }
    } else {                           // ---- gate: LN stats + weights + xp
        const int t = (b - 4224) * 8 + (tid >> 5);
        const int lane = tid & 31;
        const float* xr = x + (size_t)t * Hd;

        float4 xv[8];
        float s = 0.f, ss = 0.f, a0 = 0.f, a1 = 0.f, a2 = 0.f, a3 = 0.f;
        #pragma unroll
        for (int it = 0; it < 8; it++) {
            const int h = lane * 4 + it * 128;
            xv[it] = *(const float4*)(xr + h);
            const float4 v = xv[it];
            s  += v.x + v.y + v.z + v.w;
            ss += v.x * v.x + v.y * v.y + v.z * v.z + v.w * v.w;
            const float4* gw = (const float4*)(gw1 + h * 4);
            float4 w0r = gw[0], w1r = gw[1], w2r = gw[2], w3r = gw[3];
            a0 += v.x * w0r.x + v.y * w1r.x + v.z * w2r.x + v.w * w3r.x;
            a1 += v.x * w0r.y + v.y * w1r.y + v.z * w2r.y + v.w * w3r.y;
            a2 += v.x * w0r.z + v.y * w1r.z + v.z * w2r.z + v.w * w3r.z;
            a3 += v.x * w0r.w + v.y * w1r.w + v.z * w2r.w + v.w * w3r.w;
        }
        #pragma unroll
        for (int o = 16; o; o >>= 1) {
            s  += __shfl_xor_sync(0xffffffffu, s, o);
            ss += __shfl_xor_sync(0xffffffffu, ss, o);
            a0 += __shfl_xor_sync(0xffffffffu, a0, o);
            a1 += __shfl_xor_sync(0xffffffffu, a1, o);
            a2 += __shfl_xor_sync(0xffffffffu, a2, o);
            a3 += __shfl_xor_sync(0xffffffffu, a3, o);
        }
        const float mean = s * (1.f / Hd);
        const float var = ss * (1.f / Hd) - mean * mean;
        const float rstd = rsqrtf(var + 1e-6f);

        const int mb = t >> 7, r = t & 127;
        #pragma unroll
        for (int it = 0; it < 8; it++) {
            const int k = lane * 4 + it * 128;
            const int c = k >> 5, kb = (k >> 3) & 3, wi = k & 7;
            const float4 v = xv[it];
            uint2 o;
            o.x = hpack((v.x - mean) * rstd, (v.y - mean) * rstd);
            o.y = hpack((v.z - mean) * rstd, (v.w - mean) * rstd);
            *(uint2*)(g_xp + ((size_t)(mb * 32 + c)) * 4096 + kb * 1024 + r * 8 + wi) = o;
        }

        if (lane == 0) {
            float hv[4] = {fmaxf(a0 + gb1[0], 0.f), fmaxf(a1 + gb1[1], 0.f),
                           fmaxf(a2 + gb1[2], 0.f), fmaxf(a3 + gb1[3], 0.f)};
            float lg[4];
            #pragma unroll
            for (int e = 0; e < 4; e++) {
                float acc = gb2[e];
                #pragma unroll
                for (int d = 0; d < 4; d++) acc += hv[d] * gw2[d * 4 + e];
                if (dm[e] == 0) acc = -1e9f;
                lg[e] = acc;
            }
            const float mx = fmaxf(fmaxf(lg[0], lg[1]), fmaxf(lg[2], lg[3]));
            const float e0 = expf(lg[0] - mx), e1 = expf(lg[1] - mx);
            const float e2 = expf(lg[2] - mx), e3 = expf(lg[3] - mx);
            const float inv = 1.f / (e0 + e1 + e2 + e3);
            g_wts[4 * t + 0] = e0 * inv;
            g_wts[4 * t + 1] = e1 * inv;
            g_wts[4 * t + 2] = e2 * inv;
            g_wts[4 * t + 3] = (e1 + e2) * inv;
        }
    }
}

// ---------------- kernel: up GEMM (TMA bulk, k-chunk 64, 3x32KB stages) -------
// CTA 128m x 64f per domain. dom = wid>>2; within: 2m x 2n, warp 64m x 32f.
// Stage (32KB): A 16K | B_book 8K | B_iwslt 8K; 3 stages + mbarriers.
#define UP_SMEM  98368
#define UP_STAGE 32768
__global__ void __launch_bounds__(256, 2) k_up() {
    extern __shared__ char smem[];
    const uint32_t sm = smem_u32(smem);
    const uint32_t mbb = sm + 98304;
    const int tid = threadIdx.x, lane = tid & 31, wid = tid >> 5;
    const int mb = blockIdx.y, nb = blockIdx.x;
    const int m0 = mb * 128, n0 = nb * 64;
    const int dom = wid >> 2, wsub = wid & 3;
    const int mw = (wsub & 1) * 64, nw = (wsub >> 1) * 32;
    const int aRow = lane & 15, aK = lane >> 4;
    const int bRow = (lane & 7) + ((lane >> 4) << 3), bK = (lane >> 3) & 1;

    float acc[4][4][4];
    #pragma unroll
    for (int i = 0; i < 4; i++)
        #pragma unroll
        for (int n = 0; n < 4; n++)
            #pragma unroll
            for (int q = 0; q < 4; q++) acc[i][n][q] = 0.f;

    auto issue = [&](int c, int st) {
        const uint32_t mbar = mbb + st * 8;
        const uint32_t dst = sm + st * UP_STAGE;
        MBAR_EXPECT(mbar, 32768);
        BULK(dst, g_xp + ((size_t)(mb * 32 + c * 2)) * 4096, 16384, mbar);
        BULK(dst + 16384, g_Bp + ((size_t)(nb * 32 + c * 2)) * 2048, 8192, mbar);
        BULK(dst + 24576, g_Bp + (size_t)Fd * Hd + ((size_t)(nb * 32 + c * 2)) * 2048, 8192, mbar);
    };

    if (tid == 0) {
        #pragma unroll
        for (int st = 0; st < 3; st++) MBAR_INIT(mbb + st * 8, 1);
    }
    __syncthreads();
    if (tid == 0) { issue(0, 0); issue(1, 1); }

    int st = 0, ph = 0, st2 = 2;
    #pragma unroll 1
    for (int c = 0; c < 16; c++) {
        __syncthreads();                     // stage st2 free for reuse
        if (tid == 0 && c + 2 < 16) issue(c + 2, st2);
        MBAR_WAIT(mbb + st * 8, ph);
        const uint32_t smA = sm + st * UP_STAGE;
        const uint32_t smB = smA + 16384 + dom * 8192;
        #pragma unroll
        for (int j = 0; j < 4; j++) {
            uint32_t a[4][4];
            const uint32_t aBase = smA + (j >> 1) * 8192 +
                (((2 * (j & 1) + aK) << 7) + mw + aRow) * 16;
            #pragma unroll
            for (int i = 0; i < 4; i++) LDSM4(a[i], aBase + i * 256);
            uint32_t b[2][4];
            const uint32_t bBase = smB + (j >> 1) * 4096 +
                (((2 * (j & 1) + bK) << 6) + nw + bRow) * 16;
            #pragma unroll
            for (int nbb = 0; nbb < 2; nbb++) LDSM4(b[nbb], bBase + nbb * 256);
            #pragma unroll
            for (int i = 0; i < 4; i++)
                #pragma unroll
                for (int nbb = 0; nbb < 2; nbb++) {
                    mma_f16(acc[i][2 * nbb + 0], a[i], b[nbb][0], b[nbb][1]);
                    mma_f16(acc[i][2 * nbb + 1], a[i], b[nbb][2], b[nbb][3]);
                }
        }
        if (++st2 == 3) st2 = 0;
        if (++st == 3) { st = 0; ph ^= 1; }
    }

    // --- epilogue: dom1 -> smem (w2*relu), dom0 combines, writes packed g -----
    __syncthreads();
    const int g = lane >> 2, tq = lane & 3;
    float* ex = (float*)smem;               // [128][68] f32 = 34.8KB
    if (dom == 1) {
        #pragma unroll
        for (int i = 0; i < 4; i++) {
            const int r = mw + 16 * i + g;
            const float w2a = g_wts[4 * (m0 + r) + 2];
            const float w2b = g_wts[4 * (m0 + r + 8) + 2];
            #pragma unroll
            for (int n = 0; n < 4; n++) {
                const int col = nw + 8 * n + 2 * tq;
                const float cv0 = g_cvec[1][n0 + col], cv1 = g_cvec[1][n0 + col + 1];
                float2 v0, v1;
                v0.x = w2a * fmaxf(acc[i][n][0] + cv0, 0.f);
                v0.y = w2a * fmaxf(acc[i][n][1] + cv1, 0.f);
                v1.x = w2b * fmaxf(acc[i][n][2] + cv0, 0.f);
                v1.y = w2b * fmaxf(acc[i][n][3] + cv1, 0.f);
                *(float2*)(ex + (size_t)r * 68 + col) = v0;
                *(float2*)(ex + (size_t)(r + 8) * 68 + col) = v1;
            }
        }
    }
    __syncthreads();
    if (dom == 0) {
        #pragma unroll
        for (int i = 0; i < 4; i++) {
            const int r = mw + 16 * i + g;
            const float w1a = g_wts[4 * (m0 + r) + 1];
            const float w1b = g_wts[4 * (m0 + r + 8) + 1];
            #pragma unroll
            for (int n = 0; n < 4; n++) {
                const int col = nw + 8 * n + 2 * tq;
                const int fg = n0 + col;
                const float cv0 = g_cvec[0][fg], cv1 = g_cvec[0][fg + 1];
                const float2 s0 = *(const float2*)(ex + (size_t)r * 68 + col);
                const float2 s1 = *(const float2*)(ex + (size_t)(r + 8) * 68 + col);
                const float g0 = w1a * fmaxf(acc[i][n][0] + cv0, 0.f) + s0.x;
                const float g1 = w1a * fmaxf(acc[i][n][1] + cv1, 0.f) + s0.y;
                const float g2 = w1b * fmaxf(acc[i][n][2] + cv0, 0.f) + s1.x;
                const float g3 = w1b * fmaxf(acc[i][n][3] + cv1, 0.f) + s1.y;
                *(uint32_t*)(g_gp + gp_off(m0 + r, fg)) = hpack(g0, g1);
                *(uint32_t*)(g_gp + gp_off(m0 + r + 8, fg)) = hpack(g2, g3);
            }
        }
    }
}

// ---------------- kernel: down GEMM (TMA bulk, k-chunk 64) + residual mix -----
// CTA 128m x 128h. 8 warps 2m x 4n, warp 64m x 32h.
// Stage (32KB): A 16K | B 16K; 3 stages + mbarriers.
#define DN_SMEM  98368
#define DN_STAGE 32768
__global__ void __launch_bounds__(256, 2) k_down(const float* __restrict__ x,
                                                 const float* __restrict__ b2,
                                                 float* __restrict__ out) {
    extern __shared__ char smem[];
    const uint32_t sm = smem_u32(smem);
    const uint32_t mbb = sm + 98304;
    const int tid = threadIdx.x, lane = tid & 31, wid = tid >> 5;
    const int mb = blockIdx.y, hb = blockIdx.x;
    const int m0 = mb * 128, n0 = hb * 128;
    const int mw = (wid & 1) * 64, nw = (wid >> 1) * 32;
    const int aRow = lane & 15, aK = lane >> 4;
    const int bRow = (lane & 7) + ((lane >> 4) << 3), bK = (lane >> 3) & 1;

    float acc[4][4][4];
    #pragma unroll
    for (int i = 0; i < 4; i++)
        #pragma unroll
        for (int n = 0; n < 4; n++)
            #pragma unroll
            for (int q = 0; q < 4; q++) acc[i][n][q] = 0.f;

    auto issue = [&](int c, int st) {
        const uint32_t mbar = mbb + st * 8;
        const uint32_t dst = sm + st * DN_STAGE;
        MBAR_EXPECT(mbar, 32768);
        BULK(dst, g_gp + ((size_t)(mb * 64 + c * 2)) * 4096, 16384, mbar);
        BULK(dst + 16384, g_W2p + ((size_t)(hb * 64 + c * 2)) * 4096, 16384, mbar);
    };

    if (tid == 0) {
        #pragma unroll
        for (int st = 0; st < 3; st++) MBAR_INIT(mbb + st * 8, 1);
    }
    __syncthreads();
    if (tid == 0) { issue(0, 0); issue(1, 1); }

    int st = 0, ph = 0, st2 = 2;
    #pragma unroll 1
    for (int c = 0; c < 32; c++) {
        __syncthreads();
        if (tid == 0 && c + 2 < 32) issue(c + 2, st2);
        MBAR_WAIT(mbb + st * 8, ph);
        const uint32_t smA = sm + st * DN_STAGE;
        const uint32_t smB = smA + 16384;
        #pragma unroll
        for (int j = 0; j < 4; j++) {
            uint32_t a[4][4];
            const uint32_t aBase = smA + (j >> 1) * 8192 +
                (((2 * (j & 1) + aK) << 7) + mw + aRow) * 16;
            #pragma unroll
            for (int i = 0; i < 4; i++) LDSM4(a[i], aBase + i * 256);
            uint32_t b[2][4];
            const uint32_t bBase = smB + (j >> 1) * 8192 +
                (((2 * (j & 1) + bK) << 7) + nw + bRow) * 16;
            #pragma unroll
            for (int nbb = 0; nbb < 2; nbb++) LDSM4(b[nbb], bBase + nbb * 256);
            #pragma unroll
            for (int i = 0; i < 4; i++)
                #pragma unroll
                for (int nbb = 0; nbb < 2; nbb++) {
                    mma_f16(acc[i][2 * nbb + 0], a[i], b[nbb][0], b[nbb][1]);
                    mma_f16(acc[i][2 * nbb + 1], a[i], b[nbb][2], b[nbb][3]);
                }
        }
        if (++st2 == 3) st2 = 0;
        if (++st == 3) { st = 0; ph ^= 1; }
    }

    // --- epilogue: out = x*(1+w0) + acc + (w1+w2)*b2 --------------------------
    const int g = lane >> 2, tq = lane & 3;
    #pragma unroll
    for (int i = 0; i < 4; i++) {
        const int r0 = m0 + mw + 16 * i + g;
        const float4 wv0 = *(const float4*)&g_wts[4 * r0];
        const float4 wv1 = *(const float4*)&g_wts[4 * (r0 + 8)];
        const float xs0 = 1.f + wv0.x, w120 = wv0.w;
        const float xs1 = 1.f + wv1.x, w121 = wv1.w;
        #pragma unroll
        for (int n = 0; n < 4; n++) {
            const int h = n0 + nw + 8 * n + 2 * tq;
            const float2 xa = *(const float2*)&x[(size_t)r0 * Hd + h];
            const float2 xb = *(const float2*)&x[(size_t)(r0 + 8) * Hd + h];
            const float2 bv = *(const float2*)&b2[h];
            float2 o0, o1;
            o0.x = xa.x * xs0 + acc[i][n][0] + w120 * bv.x;
            o0.y = xa.y * xs0 + acc[i][n][1] + w120 * bv.y;
            o1.x = xb.x * xs1 + acc[i][n][2] + w121 * bv.x;
            o1.y = xb.y * xs1 + acc[i][n][3] + w121 * bv.y;
            *(float2*)&out[(size_t)r0 * Hd + h] = o0;
            *(float2*)&out[(size_t)(r0 + 8) * Hd + h] = o1;
        }
    }
}

// ---------------- launch ------------------------------------------------------
extern "C" void kernel_launch(void* const* d_in, const int* in_sizes, int n_in,
                              void* d_out, int out_size) {
    const float* x   = (const float*)d_in[0];
    const int*   dm  = (const int*)d_in[1];
    const float* gw1 = (const float*)d_in[2];
    const float* gb1 = (const float*)d_in[3];
    const float* gw2 = (const float*)d_in[4];
    const float* gb2 = (const float*)d_in[5];
    const float* sb  = (const float*)d_in[6];
    const float* bb  = (const float*)d_in[7];
    const float* si  = (const float*)d_in[8];
    const float* bi  = (const float*)d_in[9];
    const float* aw1 = (const float*)d_in[10];
    const float* ab1 = (const float*)d_in[11];
    const float* aw2 = (const float*)d_in[12];
    const float* ab2 = (const float*)d_in[13];
    float* out = (float*)d_out;

    cudaFuncSetAttribute(k_up, cudaFuncAttributeMaxDynamicSharedMemorySize, UP_SMEM);
    cudaFuncSetAttribute(k_down, cudaFuncAttributeMaxDynamicSharedMemorySize, DN_SMEM);

    k_prep<<<5248, 256>>>(x, dm, gw1, gb1, gw2, gb2, sb, si, bb, bi, aw1, ab1, aw2);
    k_up<<<dim3(Fd / 64, Td / 128), 256, UP_SMEM>>>();
    k_down<<<dim3(Hd / 128, Td / 128), 256, DN_SMEM>>>(x, ab2, out);
}

// round 11
// speedup vs baseline: 2.0797x; 1.0402x over previous
#include <cuda_runtime.h>
#include <cuda_fp16.h>
#include <cstdint>

#define Hd 1024
#define Fd 2048
#define Td 8192

// ---------------- scratch (__device__ globals; no allocs allowed) -------------
__device__ __align__(16) float g_wts[Td * 4];    // w0, w1, w2, w1+w2
__device__ __align__(16) float g_cvec[2][Fd];    // b_d @ ad_w1 + ad_b1
// tile-packed operands (blocks laid out exactly as the GEMM smem stages):
//   xp : [mb(64)][c(32)][kb(4)][r(128)][8h]      norm(x) fp16, 8KB blocks
//   Bp : [dom(2)][nb(32)][c(32)][kb(4)][f(64)][8h]  W1^T scaled, 4KB blocks
//   W2p: [hb(8)][c(64)][kb(4)][h(128)][8h]       W2^T, 8KB blocks
//   gp : [mb(64)][c(64)][kb(4)][r(128)][8h]      combined act, 8KB blocks
__device__ __align__(16) __half g_xp[(size_t)Td * Hd];
__device__ __align__(16) __half g_Bp[2 * (size_t)Fd * Hd];
__device__ __align__(16) __half g_W2p[(size_t)Hd * Fd];
__device__ __align__(16) __half g_gp[(size_t)Td * Fd];

// ---------------- PTX helpers -------------------------------------------------
__device__ __forceinline__ uint32_t smem_u32(const void* p) {
    uint32_t a;
    asm("{ .reg .u64 t; cvta.to.shared.u64 t, %1; cvt.u32.u64 %0, t; }"
        : "=r"(a) : "l"(p));
    return a;
}
#define LDSM4(r, a) \
    asm volatile("ldmatrix.sync.aligned.m8n8.x4.shared.b16 {%0,%1,%2,%3}, [%4];" \
                 : "=r"((r)[0]), "=r"((r)[1]), "=r"((r)[2]), "=r"((r)[3]) : "r"(a))
#define MBAR_INIT(a, c)  asm volatile("mbarrier.init.shared.b64 [%0], %1;" :: "r"(a), "r"((uint32_t)(c)) : "memory")
#define MBAR_EXPECT(a, tx) asm volatile("mbarrier.arrive.expect_tx.shared.b64 _, [%0], %1;" :: "r"(a), "r"((uint32_t)(tx)) : "memory")
#define MBAR_WAIT(a, p) do { \
    uint32_t _m = (a), _p = (uint32_t)(p), _d; \
    asm volatile("{\n\t.reg .pred q;\n\tmbarrier.try_wait.parity.acquire.cta.shared::cta.b64 q, [%1], %2;\n\tselp.b32 %0,1,0,q;\n\t}" \
                 : "=r"(_d) : "r"(_m), "r"(_p) : "memory"); \
    if (!_d) { \
        asm volatile("{\n\t.reg .pred q;\n\tLW_%=:\n\tmbarrier.try_wait.parity.acquire.cta.shared::cta.b64 q, [%0], %1, 0x989680;\n\t@q bra.uni LD_%=;\n\tbra.uni LW_%=;\n\tLD_%=:\n\t}" \
                     :: "r"(_m), "r"(_p) : "memory"); \
    } } while (0)
#define BULK(dst, src, sz, mb) \
    asm volatile("cp.async.bulk.shared::cluster.global.mbarrier::complete_tx::bytes [%0], [%1], %2, [%3];" \
                 :: "r"(dst), "l"(__cvta_generic_to_global(src)), "r"((uint32_t)(sz)), "r"(mb) : "memory")

__device__ __forceinline__ void mma_f16(float* d, const uint32_t* a,
                                        uint32_t b0, uint32_t b1) {
    asm volatile(
        "mma.sync.aligned.m16n8k16.row.col.f32.f16.f16.f32 "
        "{%0,%1,%2,%3}, {%4,%5,%6,%7}, {%8,%9}, {%0,%1,%2,%3};"
        : "+f"(d[0]), "+f"(d[1]), "+f"(d[2]), "+f"(d[3])
        : "r"(a[0]), "r"(a[1]), "r"(a[2]), "r"(a[3]), "r"(b0), "r"(b1));
}

__device__ __forceinline__ uint32_t hpack(float a, float b) {
    const __half2 h = __floats2half2_rn(a, b);
    return *(const uint32_t*)&h;
}
__device__ __forceinline__ size_t gp_off(int m, int f) {   // halves offset in g_gp
    return ((size_t)((m >> 7) * 64 + (f >> 5))) * 4096 +
           ((f >> 3) & 3) * 1024 + (m & 127) * 8 + (f & 7);
}

// ---------------- fused prep: trans1 | trans2 | prepc | gate ------------------
// block ranges: [0,2048) trans1, [2048,4096) trans2, [4096,4224) prepc,
//               [4224,5248) gate. All 256 threads.
__global__ void k_prep(const float* __restrict__ x, const int* __restrict__ dm,
                       const float* __restrict__ gw1, const float* __restrict__ gb1,
                       const float* __restrict__ gw2, const float* __restrict__ gb2,
                       const float* __restrict__ sb, const float* __restrict__ si,
                       const float* __restrict__ bb, const float* __restrict__ bi,
                       const float* __restrict__ aw1, const float* __restrict__ ab1,
                       const float* __restrict__ aw2) {
    __shared__ float sh[32 * 33];
    const int b = blockIdx.x;
    const int tid = threadIdx.x;

    if (b < 2048) {                    // ---- trans1: W1 -> packed, 2 domains
        const int tx = tid & 31, ty = tid >> 5;
        const int f0 = (b & 63) * 32, h0 = (b >> 6) * 32;
        #pragma unroll
        for (int i = 0; i < 4; i++) {
            const int h = h0 + ty + i * 8;
            sh[(ty + i * 8) * 33 + tx] = aw1[(size_t)h * Fd + f0 + tx];
        }
        __syncthreads();
        const int h = h0 + tx;
        const float s_b = sb[h], s_i = si[h];
        const int c = h >> 5, kb = (h >> 3) & 3, wi = h & 7;
        #pragma unroll
        for (int i = 0; i < 4; i++) {
            const int fo = f0 + ty + i * 8;
            const float w = sh[tx * 33 + ty + i * 8];
            const size_t off = ((size_t)((fo >> 6) * 32 + c)) * 2048 +
                               kb * 512 + (fo & 63) * 8 + wi;
            g_Bp[off] = __float2half_rn(w * s_b);
            g_Bp[(size_t)Fd * Hd + off] = __float2half_rn(w * s_i);
        }
    } else if (b < 4096) {             // ---- trans2: W2 -> packed
        const int bb2 = b - 2048;
        const int tx = tid & 31, ty = tid >> 5;
        const int h0 = (bb2 & 31) * 32, f0 = (bb2 >> 5) * 32;
        #pragma unroll
        for (int i = 0; i < 4; i++) {
            const int f = f0 + ty + i * 8;
            sh[(ty + i * 8) * 33 + tx] = aw2[(size_t)f * Hd + h0 + tx];
        }
        __syncthreads();
        const int f = f0 + tx;
        const int c = f >> 5, kb = (f >> 3) & 3, wi = f & 7;
        #pragma unroll
        for (int i = 0; i < 4; i++) {
            const int ho = h0 + ty + i * 8;
            const size_t off = ((size_t)((ho >> 7) * 64 + c)) * 4096 +
                               kb * 1024 + (ho & 127) * 8 + wi;
            g_W2p[off] = __float2half_rn(sh[tx * 33 + ty + i * 8]);
        }
    } else if (b < 4224) {             // ---- prepc: c_d = b_d @ W1 + ad_b1
        const int lane32 = tid & 31;
        const int ks = tid >> 5;
        const int i = (b - 4096) * 32 + lane32;
        const int d = i >> 11;
        const int f = i & (Fd - 1);
        const float* bv = d ? bi : bb;
        float acc = 0.f;
        #pragma unroll 8
        for (int h = ks * 128; h < ks * 128 + 128; h++)
            acc = fmaf(__ldg(bv + h), aw1[(size_t)h * Fd + f], acc);
        sh[ks * 32 + lane32] = acc;
        __syncthreads();
        if (ks == 0) {
            float s = sh[lane32];
            #pragma unroll
            for (int q = 1; q < 8; q++) s += sh[q * 32 + lane32];
            g_cvec[d][f] = ab1[f] + s;
        }
    } else {                           // ---- gate: LN stats + weights + xp
        const int t = (b - 4224) * 8 + (tid >> 5);
        const int lane = tid & 31;
        const float* xr = x + (size_t)t * Hd;

        float4 xv[8];
        float s = 0.f, ss = 0.f, a0 = 0.f, a1 = 0.f, a2 = 0.f, a3 = 0.f;
        #pragma unroll
        for (int it = 0; it < 8; it++) {
            const int h = lane * 4 + it * 128;
            xv[it] = *(const float4*)(xr + h);
            const float4 v = xv[it];
            s  += v.x + v.y + v.z + v.w;
            ss += v.x * v.x + v.y * v.y + v.z * v.z + v.w * v.w;
            const float4* gw = (const float4*)(gw1 + h * 4);
            float4 w0r = gw[0], w1r = gw[1], w2r = gw[2], w3r = gw[3];
            a0 += v.x * w0r.x + v.y * w1r.x + v.z * w2r.x + v.w * w3r.x;
            a1 += v.x * w0r.y + v.y * w1r.y + v.z * w2r.y + v.w * w3r.y;
            a2 += v.x * w0r.z + v.y * w1r.z + v.z * w2r.z + v.w * w3r.z;
            a3 += v.x * w0r.w + v.y * w1r.w + v.z * w2r.w + v.w * w3r.w;
        }
        #pragma unroll
        for (int o = 16; o; o >>= 1) {
            s  += __shfl_xor_sync(0xffffffffu, s, o);
            ss += __shfl_xor_sync(0xffffffffu, ss, o);
            a0 += __shfl_xor_sync(0xffffffffu, a0, o);
            a1 += __shfl_xor_sync(0xffffffffu, a1, o);
            a2 += __shfl_xor_sync(0xffffffffu, a2, o);
            a3 += __shfl_xor_sync(0xffffffffu, a3, o);
        }
        const float mean = s * (1.f / Hd);
        const float var = ss * (1.f / Hd) - mean * mean;
        const float rstd = rsqrtf(var + 1e-6f);

        const int mb = t >> 7, r = t & 127;
        #pragma unroll
        for (int it = 0; it < 8; it++) {
            const int k = lane * 4 + it * 128;
            const int c = k >> 5, kb = (k >> 3) & 3, wi = k & 7;
            const float4 v = xv[it];
            uint2 o;
            o.x = hpack((v.x - mean) * rstd, (v.y - mean) * rstd);
            o.y = hpack((v.z - mean) * rstd, (v.w - mean) * rstd);
            *(uint2*)(g_xp + ((size_t)(mb * 32 + c)) * 4096 + kb * 1024 + r * 8 + wi) = o;
        }

        if (lane == 0) {
            float hv[4] = {fmaxf(a0 + gb1[0], 0.f), fmaxf(a1 + gb1[1], 0.f),
                           fmaxf(a2 + gb1[2], 0.f), fmaxf(a3 + gb1[3], 0.f)};
            float lg[4];
            #pragma unroll
            for (int e = 0; e < 4; e++) {
                float acc = gb2[e];
                #pragma unroll
                for (int d = 0; d < 4; d++) acc += hv[d] * gw2[d * 4 + e];
                if (dm[e] == 0) acc = -1e9f;
                lg[e] = acc;
            }
            const float mx = fmaxf(fmaxf(lg[0], lg[1]), fmaxf(lg[2], lg[3]));
            const float e0 = expf(lg[0] - mx), e1 = expf(lg[1] - mx);
            const float e2 = expf(lg[2] - mx), e3 = expf(lg[3] - mx);
            const float inv = 1.f / (e0 + e1 + e2 + e3);
            g_wts[4 * t + 0] = e0 * inv;
            g_wts[4 * t + 1] = e1 * inv;
            g_wts[4 * t + 2] = e2 * inv;
            g_wts[4 * t + 3] = (e1 + e2) * inv;
        }
    }
}

// ---------------- kernel: up GEMM (TMA bulk, warp 64x64, 128 thr) -------------
// CTA 128m x 64f x 2dom, 4 warps: dom = wid>>1, mw = (wid&1)*64; warp 64m x 64f.
// Stage (32KB): A 16K | B_book 8K | B_iwslt 8K; 3 stages + mbarriers.
#define UP_SMEM  98368
#define UP_STAGE 32768
__global__ void __launch_bounds__(128, 2) k_up() {
    extern __shared__ char smem[];
    const uint32_t sm = smem_u32(smem);
    const uint32_t mbb = sm + 98304;
    const int tid = threadIdx.x, lane = tid & 31, wid = tid >> 5;
    const int mb = blockIdx.y, nb = blockIdx.x;
    const int m0 = mb * 128, n0 = nb * 64;
    const int dom = wid >> 1, mw = (wid & 1) * 64;
    const int aRow = lane & 15, aK = lane >> 4;
    const int bRow = (lane & 7) + ((lane >> 4) << 3), bK = (lane >> 3) & 1;

    float acc[4][8][4];
    #pragma unroll
    for (int i = 0; i < 4; i++)
        #pragma unroll
        for (int n = 0; n < 8; n++)
            #pragma unroll
            for (int q = 0; q < 4; q++) acc[i][n][q] = 0.f;

    auto issue = [&](int c, int st) {
        const uint32_t mbar = mbb + st * 8;
        const uint32_t dst = sm + st * UP_STAGE;
        MBAR_EXPECT(mbar, 32768);
        BULK(dst, g_xp + ((size_t)(mb * 32 + c * 2)) * 4096, 16384, mbar);
        BULK(dst + 16384, g_Bp + ((size_t)(nb * 32 + c * 2)) * 2048, 8192, mbar);
        BULK(dst + 24576, g_Bp + (size_t)Fd * Hd + ((size_t)(nb * 32 + c * 2)) * 2048, 8192, mbar);
    };

    if (tid == 0) {
        #pragma unroll
        for (int st = 0; st < 3; st++) MBAR_INIT(mbb + st * 8, 1);
    }
    __syncthreads();
    if (tid == 0) { issue(0, 0); issue(1, 1); }

    int st = 0, ph = 0, st2 = 2;
    #pragma unroll 1
    for (int c = 0; c < 16; c++) {
        __syncthreads();                     // stage st2 free for reuse
        if (tid == 0 && c + 2 < 16) issue(c + 2, st2);
        MBAR_WAIT(mbb + st * 8, ph);
        const uint32_t smA = sm + st * UP_STAGE;
        const uint32_t smB = smA + 16384 + dom * 8192;
        #pragma unroll
        for (int j = 0; j < 4; j++) {
            uint32_t a[4][4];
            const uint32_t aBase = smA + (j >> 1) * 8192 +
                (((2 * (j & 1) + aK) << 7) + mw + aRow) * 16;
            #pragma unroll
            for (int i = 0; i < 4; i++) LDSM4(a[i], aBase + i * 256);
            uint32_t b[4][4];
            const uint32_t bBase = smB + (j >> 1) * 4096 +
                (((2 * (j & 1) + bK) << 6) + bRow) * 16;
            #pragma unroll
            for (int nbb = 0; nbb < 4; nbb++) LDSM4(b[nbb], bBase + nbb * 256);
            #pragma unroll
            for (int i = 0; i < 4; i++)
                #pragma unroll
                for (int nbb = 0; nbb < 4; nbb++) {
                    mma_f16(acc[i][2 * nbb + 0], a[i], b[nbb][0], b[nbb][1]);
                    mma_f16(acc[i][2 * nbb + 1], a[i], b[nbb][2], b[nbb][3]);
                }
        }
        if (++st2 == 3) st2 = 0;
        if (++st == 3) { st = 0; ph ^= 1; }
    }

    // --- epilogue: dom1 -> smem (w2*relu), dom0 combines, writes packed g -----
    __syncthreads();
    const int g = lane >> 2, tq = lane & 3;
    float* ex = (float*)smem;               // [128][68] f32 = 34.8KB
    if (dom == 1) {
        #pragma unroll
        for (int i = 0; i < 4; i++) {
            const int r = mw + 16 * i + g;
            const float w2a = g_wts[4 * (m0 + r) + 2];
            const float w2b = g_wts[4 * (m0 + r + 8) + 2];
            #pragma unroll
            for (int n = 0; n < 8; n++) {
                const int col = 8 * n + 2 * tq;
                const float cv0 = g_cvec[1][n0 + col], cv1 = g_cvec[1][n0 + col + 1];
                float2 v0, v1;
                v0.x = w2a * fmaxf(acc[i][n][0] + cv0, 0.f);
                v0.y = w2a * fmaxf(acc[i][n][1] + cv1, 0.f);
                v1.x = w2b * fmaxf(acc[i][n][2] + cv0, 0.f);
                v1.y = w2b * fmaxf(acc[i][n][3] + cv1, 0.f);
                *(float2*)(ex + (size_t)r * 68 + col) = v0;
                *(float2*)(ex + (size_t)(r + 8) * 68 + col) = v1;
            }
        }
    }
    __syncthreads();
    if (dom == 0) {
        #pragma unroll
        for (int i = 0; i < 4; i++) {
            const int r = mw + 16 * i + g;
            const float w1a = g_wts[4 * (m0 + r) + 1];
            const float w1b = g_wts[4 * (m0 + r + 8) + 1];
            #pragma unroll
            for (int n = 0; n < 8; n++) {
                const int col = 8 * n + 2 * tq;
                const int fg = n0 + col;
                const float cv0 = g_cvec[0][fg], cv1 = g_cvec[0][fg + 1];
                const float2 s0 = *(const float2*)(ex + (size_t)r * 68 + col);
                const float2 s1 = *(const float2*)(ex + (size_t)(r + 8) * 68 + col);
                const float g0 = w1a * fmaxf(acc[i][n][0] + cv0, 0.f) + s0.x;
                const float g1 = w1a * fmaxf(acc[i][n][1] + cv1, 0.f) + s0.y;
                const float g2 = w1b * fmaxf(acc[i][n][2] + cv0, 0.f) + s1.x;
                const float g3 = w1b * fmaxf(acc[i][n][3] + cv1, 0.f) + s1.y;
                *(uint32_t*)(g_gp + gp_off(m0 + r, fg)) = hpack(g0, g1);
                *(uint32_t*)(g_gp + gp_off(m0 + r + 8, fg)) = hpack(g2, g3);
            }
        }
    }
}

// ---------------- kernel: down GEMM (TMA bulk, warp 64x64, 128 thr) -----------
// CTA 128m x 128h, 4 warps 2m x 2n, warp 64m x 64h.
// Stage (32KB): A 16K | B 16K; 3 stages + mbarriers.
#define DN_SMEM  98368
#define DN_STAGE 32768
__global__ void __launch_bounds__(128, 2) k_down(const float* __restrict__ x,
                                                 const float* __restrict__ b2,
                                                 float* __restrict__ out) {
    extern __shared__ char smem[];
    const uint32_t sm = smem_u32(smem);
    const uint32_t mbb = sm + 98304;
    const int tid = threadIdx.x, lane = tid & 31, wid = tid >> 5;
    const int mb = blockIdx.y, hb = blockIdx.x;
    const int m0 = mb * 128, n0 = hb * 128;
    const int mw = (wid & 1) * 64, nw = (wid >> 1) * 64;
    const int aRow = lane & 15, aK = lane >> 4;
    const int bRow = (lane & 7) + ((lane >> 4) << 3), bK = (lane >> 3) & 1;

    float acc[4][8][4];
    #pragma unroll
    for (int i = 0; i < 4; i++)
        #pragma unroll
        for (int n = 0; n < 8; n++)
            #pragma unroll
            for (int q = 0; q < 4; q++) acc[i][n][q] = 0.f;

    auto issue = [&](int c, int st) {
        const uint32_t mbar = mbb + st * 8;
        const uint32_t dst = sm + st * DN_STAGE;
        MBAR_EXPECT(mbar, 32768);
        BULK(dst, g_gp + ((size_t)(mb * 64 + c * 2)) * 4096, 16384, mbar);
        BULK(dst + 16384, g_W2p + ((size_t)(hb * 64 + c * 2)) * 4096, 16384, mbar);
    };

    if (tid == 0) {
        #pragma unroll
        for (int st = 0; st < 3; st++) MBAR_INIT(mbb + st * 8, 1);
    }
    __syncthreads();
    if (tid == 0) { issue(0, 0); issue(1, 1); }

    int st = 0, ph = 0, st2 = 2;
    #pragma unroll 1
    for (int c = 0; c < 32; c++) {
        __syncthreads();
        if (tid == 0 && c + 2 < 32) issue(c + 2, st2);
        MBAR_WAIT(mbb + st * 8, ph);
        const uint32_t smA = sm + st * DN_STAGE;
        const uint32_t smB = smA + 16384;
        #pragma unroll
        for (int j = 0; j < 4; j++) {
            uint32_t a[4][4];
            const uint32_t aBase = smA + (j >> 1) * 8192 +
                (((2 * (j & 1) + aK) << 7) + mw + aRow) * 16;
            #pragma unroll
            for (int i = 0; i < 4; i++) LDSM4(a[i], aBase + i * 256);
            uint32_t b[4][4];
            const uint32_t bBase = smB + (j >> 1) * 8192 +
                (((2 * (j & 1) + bK) << 7) + nw + bRow) * 16;
            #pragma unroll
            for (int nbb = 0; nbb < 4; nbb++) LDSM4(b[nbb], bBase + nbb * 256);
            #pragma unroll
            for (int i = 0; i < 4; i++)
                #pragma unroll
                for (int nbb = 0; nbb < 4; nbb++) {
                    mma_f16(acc[i][2 * nbb + 0], a[i], b[nbb][0], b[nbb][1]);
                    mma_f16(acc[i][2 * nbb + 1], a[i], b[nbb][2], b[nbb][3]);
                }
        }
        if (++st2 == 3) st2 = 0;
        if (++st == 3) { st = 0; ph ^= 1; }
    }

    // --- epilogue: out = x*(1+w0) + acc + (w1+w2)*b2 --------------------------
    const int g = lane >> 2, tq = lane & 3;
    #pragma unroll
    for (int i = 0; i < 4; i++) {
        const int r0 = m0 + mw + 16 * i + g;
        const float4 wv0 = *(const float4*)&g_wts[4 * r0];
        const float4 wv1 = *(const float4*)&g_wts[4 * (r0 + 8)];
        const float xs0 = 1.f + wv0.x, w120 = wv0.w;
        const float xs1 = 1.f + wv1.x, w121 = wv1.w;
        #pragma unroll
        for (int n = 0; n < 8; n++) {
            const int h = n0 + nw + 8 * n + 2 * tq;
            const float2 xa = *(const float2*)&x[(size_t)r0 * Hd + h];
            const float2 xb = *(const float2*)&x[(size_t)(r0 + 8) * Hd + h];
            const float2 bv = *(const float2*)&b2[h];
            float2 o0, o1;
            o0.x = xa.x * xs0 + acc[i][n][0] + w120 * bv.x;
            o0.y = xa.y * xs0 + acc[i][n][1] + w120 * bv.y;
            o1.x = xb.x * xs1 + acc[i][n][2] + w121 * bv.x;
            o1.y = xb.y * xs1 + acc[i][n][3] + w121 * bv.y;
            *(float2*)&out[(size_t)r0 * Hd + h] = o0;
            *(float2*)&out[(size_t)(r0 + 8) * Hd + h] = o1;
        }
    }
}

// ---------------- launch ------------------------------------------------------
extern "C" void kernel_launch(void* const* d_in, const int* in_sizes, int n_in,
                              void* d_out, int out_size) {
    const float* x   = (const float*)d_in[0];
    const int*   dm  = (const int*)d_in[1];
    const float* gw1 = (const float*)d_in[2];
    const float* gb1 = (const float*)d_in[3];
    const float* gw2 = (const float*)d_in[4];
    const float* gb2 = (const float*)d_in[5];
    const float* sb  = (const float*)d_in[6];
    const float* bb  = (const float*)d_in[7];
    const float* si  = (const float*)d_in[8];
    const float* bi  = (const float*)d_in[9];
    const float* aw1 = (const float*)d_in[10];
    const float* ab1 = (const float*)d_in[11];
    const float* aw2 = (const float*)d_in[12];
    const float* ab2 = (const float*)d_in[13];
    float* out = (float*)d_out;

    cudaFuncSetAttribute(k_up, cudaFuncAttributeMaxDynamicSharedMemorySize, UP_SMEM);
    cudaFuncSetAttribute(k_down, cudaFuncAttributeMaxDynamicSharedMemorySize, DN_SMEM);

    k_prep<<<5248, 256>>>(x, dm, gw1, gb1, gw2, gb2, sb, si, bb, bi, aw1, ab1, aw2);
    k_up<<<dim3(Fd / 64, Td / 128), 128, UP_SMEM>>>();
    k_down<<<dim3(Hd / 128, Td / 128), 128, DN_SMEM>>>(x, ab2, out);
}